// round 1
// baseline (speedup 1.0000x reference)
#include <cuda_runtime.h>

#define NPTS 4096
#define TPB  256
#define IPT  4
#define QPB  (TPB * IPT)

__device__ float g_accum;

static __device__ __forceinline__ unsigned long long pack2(float lo, float hi) {
    unsigned long long r;
    asm("mov.b64 %0, {%1, %2};" : "=l"(r) : "f"(lo), "f"(hi));
    return r;
}
static __device__ __forceinline__ void unpack2(unsigned long long v, float &lo, float &hi) {
    asm("mov.b64 {%0, %1}, %2;" : "=f"(lo), "=f"(hi) : "l"(v));
}
static __device__ __forceinline__ unsigned long long fma2(unsigned long long a,
                                                          unsigned long long b,
                                                          unsigned long long c) {
    unsigned long long d;
    asm("fma.rn.f32x2 %0, %1, %2, %3;" : "=l"(d) : "l"(a), "l"(b), "l"(c));
    return d;
}

// score: dist2(i,j) = |q_i|^2 + (u_j - 2 * q_i . b_j)
//   inner loop computes acc = u_j - 2*dot via 3 packed FMAs (seeded with u_j),
//   running min over j; |q_i|^2 added once at the end.
__global__ void __launch_bounds__(TPB) chamfer_main(const float* __restrict__ tpl,
                                                    const float* __restrict__ src) {
    extern __shared__ float sm[];
    float* sx = sm;
    float* sy = sm + NPTS;
    float* sz = sm + 2 * NPTS;
    float* su = sm + 3 * NPTS;

    const int batch = blockIdx.y;
    const float* Q = (blockIdx.z == 0) ? tpl : src;
    const float* D = (blockIdx.z == 0) ? src : tpl;
    Q += (size_t)batch * NPTS * 3;
    D += (size_t)batch * NPTS * 3;

    // Fill shared memory with the "database" cloud (SoA + |b|^2)
    for (int p = threadIdx.x; p < NPTS; p += TPB) {
        float x = D[3 * p + 0], y = D[3 * p + 1], z = D[3 * p + 2];
        sx[p] = x; sy[p] = y; sz[p] = z;
        su[p] = x * x + y * y + z * z;
    }
    __syncthreads();

    // Load this thread's query points, pre-pack broadcast (-2*coord)
    const int base = blockIdx.x * QPB;
    unsigned long long qx2[IPT], qy2[IPT], qz2[IPT];
    float c[IPT];
    float bestA[IPT], bestB[IPT];
#pragma unroll
    for (int k = 0; k < IPT; k++) {
        int q = base + k * TPB + threadIdx.x;
        float x = Q[3 * q + 0], y = Q[3 * q + 1], z = Q[3 * q + 2];
        c[k] = x * x + y * y + z * z;
        float mx = -2.0f * x, my = -2.0f * y, mz = -2.0f * z;
        qx2[k] = pack2(mx, mx);
        qy2[k] = pack2(my, my);
        qz2[k] = pack2(mz, mz);
        bestA[k] = 3.4e38f;
        bestB[k] = 3.4e38f;
    }

    const float4* sx4 = (const float4*)sx;
    const float4* sy4 = (const float4*)sy;
    const float4* sz4 = (const float4*)sz;
    const float4* su4 = (const float4*)su;

#pragma unroll 2
    for (int j = 0; j < NPTS / 4; j++) {
        float4 X = sx4[j], Y = sy4[j], Z = sz4[j], U = su4[j];
        unsigned long long bx01 = pack2(X.x, X.y), bx23 = pack2(X.z, X.w);
        unsigned long long by01 = pack2(Y.x, Y.y), by23 = pack2(Y.z, Y.w);
        unsigned long long bz01 = pack2(Z.x, Z.y), bz23 = pack2(Z.z, Z.w);
        unsigned long long u01  = pack2(U.x, U.y), u23  = pack2(U.z, U.w);
#pragma unroll
        for (int k = 0; k < IPT; k++) {
            unsigned long long a01 = fma2(qz2[k], bz01, u01);
            a01 = fma2(qy2[k], by01, a01);
            a01 = fma2(qx2[k], bx01, a01);
            unsigned long long a23 = fma2(qz2[k], bz23, u23);
            a23 = fma2(qy2[k], by23, a23);
            a23 = fma2(qx2[k], bx23, a23);
            float l0, h0, l1, h1;
            unpack2(a01, l0, h0);
            unpack2(a23, l1, h1);
            bestA[k] = fminf(bestA[k], fminf(l0, l1));
            bestB[k] = fminf(bestB[k], fminf(h0, h1));
        }
    }

    // Per-thread: add |q|^2, clamp, sqrt, sum over IPT queries
    float s = 0.0f;
#pragma unroll
    for (int k = 0; k < IPT; k++) {
        float d = c[k] + fminf(bestA[k], bestB[k]);
        d = fmaxf(d, 0.0f);
        s += sqrtf(d);
    }

    // warp reduce
#pragma unroll
    for (int o = 16; o; o >>= 1) s += __shfl_xor_sync(0xffffffffu, s, o);

    __syncthreads();  // everyone done reading smem; safe to reuse
    if ((threadIdx.x & 31) == 0) sm[threadIdx.x >> 5] = s;
    __syncthreads();
    if (threadIdx.x == 0) {
        float t = 0.0f;
#pragma unroll
        for (int w = 0; w < TPB / 32; w++) t += sm[w];
        atomicAdd(&g_accum, t);
    }
}

__global__ void chamfer_init() { g_accum = 0.0f; }

__global__ void chamfer_fin(float* out) {
    // result = (mean1 + mean2)/2 = total_sum / (2 * 16 * 4096)
    out[0] = g_accum * (1.0f / 131072.0f);
}

extern "C" void kernel_launch(void* const* d_in, const int* in_sizes, int n_in,
                              void* d_out, int out_size) {
    const float* tpl = (const float*)d_in[0];
    const float* src = (const float*)d_in[1];
    (void)in_sizes; (void)n_in; (void)out_size;

    cudaFuncSetAttribute(chamfer_main, cudaFuncAttributeMaxDynamicSharedMemorySize,
                         4 * NPTS * (int)sizeof(float));

    chamfer_init<<<1, 1>>>();
    dim3 grid(NPTS / QPB, 16, 2);
    chamfer_main<<<grid, TPB, 4 * NPTS * sizeof(float)>>>(tpl, src);
    chamfer_fin<<<1, 1>>>((float*)d_out);
}

// round 2
// speedup vs baseline: 1.1565x; 1.1565x over previous
#include <cuda_runtime.h>

#define NPTS    4096
#define NB      16          // batches
#define TPB     512
#define IPT     2           // queries per thread
#define QCHUNK  128         // queries per work item
#define NSLICE  8           // j-range slices per block (512 threads / 64 qslots)
#define JQ_PER_SLICE (NPTS / NSLICE / 4)   // 128 quads = 512 points per slice
#define NITEMS  (2 * NB * (NPTS / QCHUNK)) // 2*16*32 = 1024
#define GRID    148

__device__ float g_accum;

typedef unsigned long long u64;

static __device__ __forceinline__ u64 pack2(float lo, float hi) {
    u64 r;
    asm("mov.b64 %0, {%1, %2};" : "=l"(r) : "f"(lo), "f"(hi));
    return r;
}
static __device__ __forceinline__ void unpack2(u64 v, float &lo, float &hi) {
    asm("mov.b64 {%0, %1}, %2;" : "=f"(lo), "=f"(hi) : "l"(v));
}
static __device__ __forceinline__ u64 fma2(u64 a, u64 b, u64 c) {
    u64 d;
    asm("fma.rn.f32x2 %0, %1, %2, %3;" : "=l"(d) : "l"(a), "l"(b), "l"(c));
    return d;
}

// dist2(i,j) = |q_i|^2 + (|b_j|^2 - 2 q_i . b_j); min over j of the paren term,
// |q|^2 added once at combine time. 3 packed FMAs per 2 j-points.
__global__ void __launch_bounds__(TPB) chamfer_main(const float* __restrict__ tpl,
                                                    const float* __restrict__ src) {
    extern __shared__ float sm[];
    float* sx = sm;
    float* sy = sm + NPTS;
    float* sz = sm + 2 * NPTS;
    float* su = sm + 3 * NPTS;
    float* pmin = sm + 4 * NPTS;            // [NSLICE][QCHUNK] = 1024 floats

    const int tid   = threadIdx.x;
    const int qi    = tid & 63;             // query sub-index within chunk (0..63)
    const int slice = tid >> 6;             // j-slice (0..7)

    // Static contiguous item range for this block (items ordered cloud-major
    // so smem refills are rare within a block's range).
    const int lo = (int)(((long long)blockIdx.x * NITEMS) / GRID);
    const int hi = (int)(((long long)(blockIdx.x + 1) * NITEMS) / GRID);

    int cached_cloud = -1;
    float s = 0.0f;

    for (int item = lo; item < hi; item++) {
        const int qc    = item & 31;        // 32 qchunks per cloud
        const int cloud = item >> 5;        // dir*16 + batch
        const int batch = cloud & 15;
        const int dir   = cloud >> 4;

        const float* Q = (dir == 0) ? tpl : src;
        const float* D = (dir == 0) ? src : tpl;
        Q += (size_t)batch * NPTS * 3;
        D += (size_t)batch * NPTS * 3;

        if (cloud != cached_cloud) {
            // previous item's compute reads of sm[] are fenced by the trailing
            // __syncthreads() of the prior iteration (or this is the first item)
            for (int p = tid; p < NPTS; p += TPB) {
                float x = D[3 * p + 0], y = D[3 * p + 1], z = D[3 * p + 2];
                sx[p] = x; sy[p] = y; sz[p] = z;
                su[p] = x * x + y * y + z * z;
            }
            cached_cloud = cloud;
            __syncthreads();
        }

        // ---- compute phase: this thread scans its j-slice for 2 queries ----
        const int qbase = qc * QCHUNK;
        const int q0 = qbase + qi;
        const int q1 = qbase + 64 + qi;

        float x0 = Q[3 * q0 + 0], y0 = Q[3 * q0 + 1], z0 = Q[3 * q0 + 2];
        float x1 = Q[3 * q1 + 0], y1 = Q[3 * q1 + 1], z1 = Q[3 * q1 + 2];
        u64 qx0 = pack2(-2.0f * x0, -2.0f * x0);
        u64 qy0 = pack2(-2.0f * y0, -2.0f * y0);
        u64 qz0 = pack2(-2.0f * z0, -2.0f * z0);
        u64 qx1 = pack2(-2.0f * x1, -2.0f * x1);
        u64 qy1 = pack2(-2.0f * y1, -2.0f * y1);
        u64 qz1 = pack2(-2.0f * z1, -2.0f * z1);

        float b0A = 3.4e38f, b0B = 3.4e38f, b1A = 3.4e38f, b1B = 3.4e38f;

        // ulonglong2 views: each element = 4 consecutive points, halves are
        // naturally-packed f32x2 operands (no pack MOVs).
        const ulonglong2* px = (const ulonglong2*)sx + slice * JQ_PER_SLICE;
        const ulonglong2* py = (const ulonglong2*)sy + slice * JQ_PER_SLICE;
        const ulonglong2* pz = (const ulonglong2*)sz + slice * JQ_PER_SLICE;
        const ulonglong2* pu = (const ulonglong2*)su + slice * JQ_PER_SLICE;

#pragma unroll 4
        for (int j = 0; j < JQ_PER_SLICE; j++) {
            ulonglong2 bx = px[j], by = py[j], bz = pz[j], bu = pu[j];

            u64 a01 = fma2(qz0, bz.x, bu.x);
            a01 = fma2(qy0, by.x, a01);
            a01 = fma2(qx0, bx.x, a01);
            u64 a23 = fma2(qz0, bz.y, bu.y);
            a23 = fma2(qy0, by.y, a23);
            a23 = fma2(qx0, bx.y, a23);

            u64 c01 = fma2(qz1, bz.x, bu.x);
            c01 = fma2(qy1, by.x, c01);
            c01 = fma2(qx1, bx.x, c01);
            u64 c23 = fma2(qz1, bz.y, bu.y);
            c23 = fma2(qy1, by.y, c23);
            c23 = fma2(qx1, bx.y, c23);

            float l0, h0, l1, h1;
            unpack2(a01, l0, h0);
            unpack2(a23, l1, h1);
            b0A = fminf(b0A, fminf(l0, l1));
            b0B = fminf(b0B, fminf(h0, h1));
            unpack2(c01, l0, h0);
            unpack2(c23, l1, h1);
            b1A = fminf(b1A, fminf(l0, l1));
            b1B = fminf(b1B, fminf(h0, h1));
        }

        pmin[slice * QCHUNK + qi]      = fminf(b0A, b0B);
        pmin[slice * QCHUNK + 64 + qi] = fminf(b1A, b1B);
        __syncthreads();

        // ---- combine phase: threads 0..127 fold the 8 slices ----
        if (tid < QCHUNK) {
            float m = pmin[tid];
#pragma unroll
            for (int sl = 1; sl < NSLICE; sl++)
                m = fminf(m, pmin[sl * QCHUNK + tid]);
            int qg = qbase + tid;
            float x = Q[3 * qg + 0], y = Q[3 * qg + 1], z = Q[3 * qg + 2];
            float c = x * x + y * y + z * z;
            float d = fmaxf(c + m, 0.0f);
            s += sqrtf(d);
        }
        __syncthreads();   // pmin reuse + smem refill safety for next item
    }

    // ---- block reduction (once per block) ----
#pragma unroll
    for (int o = 16; o; o >>= 1) s += __shfl_xor_sync(0xffffffffu, s, o);
    if ((tid & 31) == 0) pmin[tid >> 5] = s;
    __syncthreads();
    if (tid == 0) {
        float t = 0.0f;
#pragma unroll
        for (int w = 0; w < TPB / 32; w++) t += pmin[w];
        atomicAdd(&g_accum, t);
    }
}

__global__ void chamfer_init() { g_accum = 0.0f; }

__global__ void chamfer_fin(float* out) {
    out[0] = g_accum * (1.0f / 131072.0f);   // / (2 * 16 * 4096)
}

extern "C" void kernel_launch(void* const* d_in, const int* in_sizes, int n_in,
                              void* d_out, int out_size) {
    const float* tpl = (const float*)d_in[0];
    const float* src = (const float*)d_in[1];
    (void)in_sizes; (void)n_in; (void)out_size;

    const int smem = (4 * NPTS + NSLICE * QCHUNK) * (int)sizeof(float);
    cudaFuncSetAttribute(chamfer_main, cudaFuncAttributeMaxDynamicSharedMemorySize, smem);

    chamfer_init<<<1, 1>>>();
    chamfer_main<<<GRID, TPB, smem>>>(tpl, src);
    chamfer_fin<<<1, 1>>>((float*)d_out);
}

// round 4
// speedup vs baseline: 1.2384x; 1.0709x over previous
#include <cuda_runtime.h>

#define NPTS    4096
#define NB      16
#define TPB     512
#define QCHUNK  128
#define IPT     4
#define NQT     32                          // q-threads (QCHUNK / IPT)
#define NSLICE  16                          // TPB / NQT
#define SLICE_QUADS (NPTS / NSLICE / 4)     // 64 quads = 256 points per slice
#define NITEMS  (2 * NB * (NPTS / QCHUNK))  // 1024
#define GRID    148

__device__ float g_accum;      // zero at entry/exit of every launch
__device__ unsigned g_count;   // zero at entry/exit of every launch

typedef unsigned long long u64;

static __device__ __forceinline__ u64 bcast2(float v) {
    u64 r;
    asm("mov.b64 %0, {%1, %1};" : "=l"(r) : "f"(v));
    return r;
}
static __device__ __forceinline__ void unpack2(u64 v, float &lo, float &hi) {
    asm("mov.b64 {%0, %1}, %2;" : "=f"(lo), "=f"(hi) : "l"(v));
}
static __device__ __forceinline__ u64 fma2(u64 a, u64 b, u64 c) {
    u64 d;
    asm("fma.rn.f32x2 %0, %1, %2, %3;" : "=l"(d) : "l"(a), "l"(b), "l"(c));
    return d;
}

// dist2(i,j) = |q_i|^2 + (|b_j|^2 - 2 q_i . b_j)
// inner loop: packed acc = u_j - 2*dot via 3 FFMA2 per 2 points, scalar FMNMX
// running min; |q|^2 added once at combine.
__global__ void __launch_bounds__(TPB) chamfer_main(const float* __restrict__ tpl,
                                                    const float* __restrict__ src,
                                                    float* __restrict__ out) {
    extern __shared__ float sm[];
    float* sx = sm;
    float* sy = sm + NPTS;
    float* sz = sm + 2 * NPTS;
    float* su = sm + 3 * NPTS;
    float* pmin = sm + 4 * NPTS;            // [NSLICE][QCHUNK] = 2048 floats

    const int tid   = threadIdx.x;
    const int qi    = tid & (NQT - 1);      // 0..31
    const int slice = tid >> 5;             // 0..15 (== warp id)

    const int lo = (int)(((long long)blockIdx.x * NITEMS) / GRID);
    const int hi = (int)(((long long)(blockIdx.x + 1) * NITEMS) / GRID);

    int cached_cloud = -1;
    float s = 0.0f;

    for (int item = lo; item < hi; item++) {
        const int qc    = item & 31;        // 32 qchunks per cloud
        const int cloud = item >> 5;
        const int batch = cloud & 15;
        const int dir   = cloud >> 4;

        const float* Q = (dir == 0) ? tpl : src;
        const float* D = (dir == 0) ? src : tpl;
        Q += (size_t)batch * NPTS * 3;
        D += (size_t)batch * NPTS * 3;

        if (cloud != cached_cloud) {
            for (int p = tid; p < NPTS; p += TPB) {
                float x = D[3 * p + 0], y = D[3 * p + 1], z = D[3 * p + 2];
                sx[p] = x; sy[p] = y; sz[p] = z;
                su[p] = x * x + y * y + z * z;
            }
            cached_cloud = cloud;
            __syncthreads();
        }

        const int qbase = qc * QCHUNK;

        u64 qx[IPT], qy[IPT], qz[IPT];
        float bA[IPT], bB[IPT];
#pragma unroll
        for (int k = 0; k < IPT; k++) {
            int q = qbase + k * NQT + qi;
            qx[k] = bcast2(-2.0f * Q[3 * q + 0]);
            qy[k] = bcast2(-2.0f * Q[3 * q + 1]);
            qz[k] = bcast2(-2.0f * Q[3 * q + 2]);
            bA[k] = 3.4e38f;
            bB[k] = 3.4e38f;
        }

        const ulonglong2* px = (const ulonglong2*)sx + slice * SLICE_QUADS;
        const ulonglong2* py = (const ulonglong2*)sy + slice * SLICE_QUADS;
        const ulonglong2* pz = (const ulonglong2*)sz + slice * SLICE_QUADS;
        const ulonglong2* pu = (const ulonglong2*)su + slice * SLICE_QUADS;

#pragma unroll 2
        for (int j = 0; j < SLICE_QUADS; j++) {
            ulonglong2 bx = px[j], by = py[j], bz = pz[j], bu = pu[j];
#pragma unroll
            for (int k = 0; k < IPT; k++) {
                u64 a01 = fma2(qz[k], bz.x, bu.x);
                a01 = fma2(qy[k], by.x, a01);
                a01 = fma2(qx[k], bx.x, a01);
                u64 a23 = fma2(qz[k], bz.y, bu.y);
                a23 = fma2(qy[k], by.y, a23);
                a23 = fma2(qx[k], bx.y, a23);
                float l0, h0, l1, h1;
                unpack2(a01, l0, h0);
                unpack2(a23, l1, h1);
                bA[k] = fminf(bA[k], fminf(l0, l1));
                bB[k] = fminf(bB[k], fminf(h0, h1));
            }
        }

#pragma unroll
        for (int k = 0; k < IPT; k++)
            pmin[slice * QCHUNK + k * NQT + qi] = fminf(bA[k], bB[k]);
        __syncthreads();

        // combine: threads 0..127 fold the 16 slices for their query
        if (tid < QCHUNK) {
            float m = pmin[tid];
#pragma unroll
            for (int sl = 1; sl < NSLICE; sl++)
                m = fminf(m, pmin[sl * QCHUNK + tid]);
            int qg = qbase + tid;
            float x = Q[3 * qg + 0], y = Q[3 * qg + 1], z = Q[3 * qg + 2];
            float c = x * x + y * y + z * z;
            s += sqrtf(fmaxf(c + m, 0.0f));
        }
        __syncthreads();   // pmin reuse / smem refill safety
    }

    // block reduction
#pragma unroll
    for (int o = 16; o; o >>= 1) s += __shfl_xor_sync(0xffffffffu, s, o);
    if ((tid & 31) == 0) pmin[tid >> 5] = s;
    __syncthreads();

    if (tid == 0) {
        float t = 0.0f;
#pragma unroll
        for (int w = 0; w < TPB / 32; w++) t += pmin[w];
        atomicAdd(&g_accum, t);
        __threadfence();
        unsigned old = atomicAdd(&g_count, 1u);
        if (old == GRID - 1) {
            __threadfence();
            float total = atomicAdd(&g_accum, 0.0f);   // atomic read
            out[0] = total * (1.0f / 131072.0f);       // / (2*16*4096)
            g_accum = 0.0f;                            // reset for next replay
            __threadfence();
            atomicExch(&g_count, 0u);
        }
    }
}

extern "C" void kernel_launch(void* const* d_in, const int* in_sizes, int n_in,
                              void* d_out, int out_size) {
    const float* tpl = (const float*)d_in[0];
    const float* src = (const float*)d_in[1];
    (void)in_sizes; (void)n_in; (void)out_size;

    const int smem = (4 * NPTS + NSLICE * QCHUNK) * (int)sizeof(float);
    cudaFuncSetAttribute(chamfer_main, cudaFuncAttributeMaxDynamicSharedMemorySize, smem);

    chamfer_main<<<GRID, TPB, smem>>>(tpl, src, (float*)d_out);
}